// round 1
// baseline (speedup 1.0000x reference)
#include <cuda_runtime.h>

#define NN 50000
#define EE 800000
#define DD 128
#define BM 64
#define BK 16
#define APAD 4
#define EPS 1e-5f
#define SQRTD 11.313708498984761f

__device__ float g_x[(long long)NN * DD];
__device__ float g_agg[(long long)NN * DD];

__device__ __forceinline__ float4 ld4(const float* __restrict__ p) {
    return *reinterpret_cast<const float4*>(p);
}

// ---------------- embedding + LayerNorm ----------------
// One warp per node row. lane holds 4 of the 128 features.
__global__ void __launch_bounds__(256) embed_ln_kernel(
    const float* __restrict__ node_emb, const int* __restrict__ pos,
    const float* __restrict__ pos_table, const float* __restrict__ gamma,
    const float* __restrict__ beta)
{
    int row  = blockIdx.x * 8 + (threadIdx.x >> 5);
    int lane = threadIdx.x & 31;
    int p = __ldg(pos + row);
    float4 a  = ld4(node_emb + (long long)row * DD + lane * 4);
    float4 pe = ld4(pos_table + (long long)p * DD + lane * 4);
    float v0 = a.x * SQRTD + pe.x;
    float v1 = a.y * SQRTD + pe.y;
    float v2 = a.z * SQRTD + pe.z;
    float v3 = a.w * SQRTD + pe.w;
    float s  = v0 + v1 + v2 + v3;
    float sq = v0*v0 + v1*v1 + v2*v2 + v3*v3;
    #pragma unroll
    for (int off = 16; off; off >>= 1) {
        s  += __shfl_xor_sync(0xffffffffu, s,  off);
        sq += __shfl_xor_sync(0xffffffffu, sq, off);
    }
    float mean = s * (1.0f / DD);
    float var  = sq * (1.0f / DD) - mean * mean;
    float rstd = rsqrtf(var + EPS);
    float4 g = ld4(gamma + lane * 4);
    float4 b = ld4(beta  + lane * 4);
    float4 o;
    o.x = (v0 - mean) * rstd * g.x + b.x;
    o.y = (v1 - mean) * rstd * g.y + b.y;
    o.z = (v2 - mean) * rstd * g.z + b.z;
    o.w = (v3 - mean) * rstd * g.w + b.w;
    *reinterpret_cast<float4*>(g_x + (long long)row * DD + lane * 4) = o;
}

// ---------------- zero the aggregation buffer ----------------
__global__ void __launch_bounds__(256) zero_agg_kernel()
{
    long long i = (long long)blockIdx.x * 256 + threadIdx.x;
    reinterpret_cast<float4*>(g_agg)[i] = make_float4(0.f, 0.f, 0.f, 0.f);
}

// ---------------- edge scatter-add (warp per edge, vector red) ----------------
__global__ void __launch_bounds__(256) scatter_kernel(const int* __restrict__ edge)
{
    int e = (int)((blockIdx.x * 256u + threadIdx.x) >> 5);
    if (e >= EE) return;
    int lane = threadIdx.x & 31;
    int src = __ldg(edge + e);
    int dst = __ldg(edge + EE + e);
    float4 v = ld4(g_x + (long long)src * DD + lane * 4);
    float* p = g_agg + (long long)dst * DD + lane * 4;
    asm volatile("red.global.add.v4.f32 [%0], {%1, %2, %3, %4};"
                 :: "l"(p), "f"(v.x), "f"(v.y), "f"(v.z), "f"(v.w)
                 : "memory");
}

// ---------------- fused dual-GEMM + bias + ReLU + residual + LayerNorm ----------
// h = agg @ Wl + bl + x @ Wr ; h = relu(h); out = LN(h + x)
// Block: 64 rows x 128 cols, 256 threads, 8x4 per-thread microtile.
// Thread (ty = tid>>5, tx = tid&31): rows ty*8..ty*8+7, cols tx*4..tx*4+3.
// All 32 lanes of warp ty cover the full 128 cols of 8 rows -> warp-shuffle LN.
__global__ void __launch_bounds__(256) sage_layer_kernel(
    const float* __restrict__ Wl, const float* __restrict__ bl,
    const float* __restrict__ Wr, const float* __restrict__ gamma,
    const float* __restrict__ beta, float* __restrict__ out_opt)
{
    __shared__ float sA[BK][BM + APAD];
    __shared__ float sX[BK][BM + APAD];
    __shared__ float sWl[BK][DD];
    __shared__ float sWr[BK][DD];

    int tid = threadIdx.x;
    int tx = tid & 31;
    int ty = tid >> 5;
    int row0 = blockIdx.x * BM;

    // global A-tile load mapping: lr = row in tile (0..63), lc = col chunk (0,4,8,12)
    int lr = tid >> 2;
    int lc = (tid & 3) * 4;
    long long abase = (long long)(row0 + lr) * DD + lc;
    bool rvalid = (row0 + lr) < NN;

    // W-tile load mapping: each warp loads one row-pair of the 16x128 chunk
    int wrow = tid >> 5;
    int wcol = (tid & 31) * 4;

    float acc[8][4];
    #pragma unroll
    for (int i = 0; i < 8; i++)
        #pragma unroll
        for (int j = 0; j < 4; j++) acc[i][j] = 0.f;

    for (int k0 = 0; k0 < DD; k0 += BK) {
        float4 av = rvalid ? ld4(g_agg + abase + k0) : make_float4(0,0,0,0);
        float4 xv = rvalid ? ld4(g_x  + abase + k0) : make_float4(0,0,0,0);
        sA[lc+0][lr] = av.x; sA[lc+1][lr] = av.y; sA[lc+2][lr] = av.z; sA[lc+3][lr] = av.w;
        sX[lc+0][lr] = xv.x; sX[lc+1][lr] = xv.y; sX[lc+2][lr] = xv.z; sX[lc+3][lr] = xv.w;
        *reinterpret_cast<float4*>(&sWl[wrow][wcol])     = ld4(Wl + (long long)(k0 + wrow) * DD + wcol);
        *reinterpret_cast<float4*>(&sWl[wrow + 8][wcol]) = ld4(Wl + (long long)(k0 + wrow + 8) * DD + wcol);
        *reinterpret_cast<float4*>(&sWr[wrow][wcol])     = ld4(Wr + (long long)(k0 + wrow) * DD + wcol);
        *reinterpret_cast<float4*>(&sWr[wrow + 8][wcol]) = ld4(Wr + (long long)(k0 + wrow + 8) * DD + wcol);
        __syncthreads();

        #pragma unroll
        for (int k = 0; k < BK; k++) {
            float4 wl = *reinterpret_cast<const float4*>(&sWl[k][tx * 4]);
            float4 wr = *reinterpret_cast<const float4*>(&sWr[k][tx * 4]);
            float4 a0 = *reinterpret_cast<const float4*>(&sA[k][ty * 8]);
            float4 a1 = *reinterpret_cast<const float4*>(&sA[k][ty * 8 + 4]);
            float4 x0 = *reinterpret_cast<const float4*>(&sX[k][ty * 8]);
            float4 x1 = *reinterpret_cast<const float4*>(&sX[k][ty * 8 + 4]);
            float am[8] = {a0.x, a0.y, a0.z, a0.w, a1.x, a1.y, a1.z, a1.w};
            float xm[8] = {x0.x, x0.y, x0.z, x0.w, x1.x, x1.y, x1.z, x1.w};
            #pragma unroll
            for (int i = 0; i < 8; i++) {
                acc[i][0] += am[i] * wl.x + xm[i] * wr.x;
                acc[i][1] += am[i] * wl.y + xm[i] * wr.y;
                acc[i][2] += am[i] * wl.z + xm[i] * wr.z;
                acc[i][3] += am[i] * wl.w + xm[i] * wr.w;
            }
        }
        __syncthreads();
    }

    float* dst = out_opt ? out_opt : g_x;
    float4 blv = ld4(bl    + tx * 4);
    float4 gv  = ld4(gamma + tx * 4);
    float4 bv  = ld4(beta  + tx * 4);

    #pragma unroll
    for (int i = 0; i < 8; i++) {
        int row = row0 + ty * 8 + i;
        if (row >= NN) continue;  // uniform within warp (all lanes share ty, i)
        float4 xr = ld4(g_x + (long long)row * DD + tx * 4);
        float t0 = fmaxf(acc[i][0] + blv.x, 0.f) + xr.x;
        float t1 = fmaxf(acc[i][1] + blv.y, 0.f) + xr.y;
        float t2 = fmaxf(acc[i][2] + blv.z, 0.f) + xr.z;
        float t3 = fmaxf(acc[i][3] + blv.w, 0.f) + xr.w;
        float s  = t0 + t1 + t2 + t3;
        float sq = t0*t0 + t1*t1 + t2*t2 + t3*t3;
        #pragma unroll
        for (int off = 16; off; off >>= 1) {
            s  += __shfl_xor_sync(0xffffffffu, s,  off);
            sq += __shfl_xor_sync(0xffffffffu, sq, off);
        }
        float mean = s * (1.0f / DD);
        float var  = sq * (1.0f / DD) - mean * mean;
        float rstd = rsqrtf(var + EPS);
        float4 o;
        o.x = (t0 - mean) * rstd * gv.x + bv.x;
        o.y = (t1 - mean) * rstd * gv.y + bv.y;
        o.z = (t2 - mean) * rstd * gv.z + bv.z;
        o.w = (t3 - mean) * rstd * gv.w + bv.w;
        *reinterpret_cast<float4*>(dst + (long long)row * DD + tx * 4) = o;
    }
}

extern "C" void kernel_launch(void* const* d_in, const int* in_sizes, int n_in,
                              void* d_out, int out_size)
{
    const float* node_emb  = (const float*)d_in[0];
    const int*   pos       = (const int*)  d_in[1];
    const int*   edge      = (const int*)  d_in[2];
    const float* pos_table = (const float*)d_in[3];
    const float* Wl        = (const float*)d_in[4];
    const float* bl        = (const float*)d_in[5];
    const float* Wr        = (const float*)d_in[6];
    const float* emb_g     = (const float*)d_in[7];
    const float* emb_b     = (const float*)d_in[8];
    const float* hid_g     = (const float*)d_in[9];
    const float* hid_b     = (const float*)d_in[10];
    float* out = (float*)d_out;

    embed_ln_kernel<<<NN / 8, 256>>>(node_emb, pos, pos_table, emb_g, emb_b);

    const int gemm_grid = (NN + BM - 1) / BM;       // 782
    const int zero_grid = (NN * DD / 4) / 256;      // 6250
    const int scat_grid = EE / 8;                   // 100000

    for (int l = 0; l < 3; l++) {
        zero_agg_kernel<<<zero_grid, 256>>>();
        scatter_kernel<<<scat_grid, 256>>>(edge);
        float* outp = (l == 2) ? out : nullptr;
        sage_layer_kernel<<<gemm_grid, 256>>>(
            Wl + (long long)l * DD * DD, bl + l * DD,
            Wr + (long long)l * DD * DD, hid_g + l * DD, hid_b + l * DD,
            outp);
    }
}

// round 2
// speedup vs baseline: 1.1613x; 1.1613x over previous
#include <cuda_runtime.h>
#include <cuda_bf16.h>

#define NN 50000
#define NP 50176          // padded rows (392*128)
#define EE 800000
#define DD 128
#define EPS 1e-5f
#define SQRTD 11.313708498984761f

typedef unsigned int u32;

__device__ float g_x[(long long)NP * DD];
__device__ float g_agg[(long long)NP * DD];
__device__ __nv_bfloat16 g_xh[(long long)NP * DD];
__device__ __nv_bfloat16 g_xl[(long long)NP * DD];
__device__ __nv_bfloat16 g_ah[(long long)NP * DD];
__device__ __nv_bfloat16 g_al[(long long)NP * DD];
// weights, split + transposed: [layer][n][k]
__device__ __nv_bfloat16 g_Wlh[3 * DD * DD];
__device__ __nv_bfloat16 g_Wll[3 * DD * DD];
__device__ __nv_bfloat16 g_Wrh[3 * DD * DD];
__device__ __nv_bfloat16 g_Wrl[3 * DD * DD];

__device__ __forceinline__ float4 ld4(const float* __restrict__ p) {
    return *reinterpret_cast<const float4*>(p);
}

__device__ __forceinline__ void split2(float a, float b, u32& hi, u32& lo) {
    __nv_bfloat162 h = __floats2bfloat162_rn(a, b);
    float ra = a - __bfloat162float(h.x);
    float rb = b - __bfloat162float(h.y);
    __nv_bfloat162 l = __floats2bfloat162_rn(ra, rb);
    hi = *reinterpret_cast<u32*>(&h);
    lo = *reinterpret_cast<u32*>(&l);
}

__device__ __forceinline__ void mma16816(float* d, const u32* a, const u32* b) {
    asm volatile(
        "mma.sync.aligned.m16n8k16.row.col.f32.bf16.bf16.f32 "
        "{%0,%1,%2,%3}, {%4,%5,%6,%7}, {%8,%9}, {%0,%1,%2,%3};"
        : "+f"(d[0]), "+f"(d[1]), "+f"(d[2]), "+f"(d[3])
        : "r"(a[0]), "r"(a[1]), "r"(a[2]), "r"(a[3]), "r"(b[0]), "r"(b[1]));
}

// ---------------- weight split + transpose (runs once per launch) ------------
__global__ void __launch_bounds__(256) split_w_kernel(
    const float* __restrict__ Wl, const float* __restrict__ Wr)
{
    int idx = blockIdx.x * 256 + threadIdx.x;       // 3*128*128 = 49152
    if (idx >= 3 * DD * DD) return;
    int l = idx / (DD * DD);
    int k = (idx / DD) % DD;
    int n = idx % DD;
    int dst = l * DD * DD + n * DD + k;             // transposed [l][n][k]
    float wl = Wl[idx];
    __nv_bfloat16 h = __float2bfloat16(wl);
    g_Wlh[dst] = h;
    g_Wll[dst] = __float2bfloat16(wl - __bfloat162float(h));
    float wr = Wr[idx];
    __nv_bfloat16 h2 = __float2bfloat16(wr);
    g_Wrh[dst] = h2;
    g_Wrl[dst] = __float2bfloat16(wr - __bfloat162float(h2));
}

// ---------------- zero padding rows of x buffers (once per launch) -----------
__global__ void __launch_bounds__(256) pad_zero_kernel()
{
    int i = blockIdx.x * 256 + threadIdx.x;         // (NP-NN)*128 = 22528
    if (i >= (NP - NN) * DD) return;
    long long off = (long long)NN * DD + i;
    g_x[off] = 0.f;
    g_xh[off] = __float2bfloat16(0.f);
    g_xl[off] = __float2bfloat16(0.f);
}

// ---------------- embedding + LayerNorm (writes fp32 + bf16 hi/lo) ----------
__global__ void __launch_bounds__(256) embed_ln_kernel(
    const float* __restrict__ node_emb, const int* __restrict__ pos,
    const float* __restrict__ pos_table, const float* __restrict__ gamma,
    const float* __restrict__ beta)
{
    int row  = blockIdx.x * 8 + (threadIdx.x >> 5);
    int lane = threadIdx.x & 31;
    int p = __ldg(pos + row);
    float4 a  = ld4(node_emb + (long long)row * DD + lane * 4);
    float4 pe = ld4(pos_table + (long long)p * DD + lane * 4);
    float v0 = a.x * SQRTD + pe.x;
    float v1 = a.y * SQRTD + pe.y;
    float v2 = a.z * SQRTD + pe.z;
    float v3 = a.w * SQRTD + pe.w;
    float s  = v0 + v1 + v2 + v3;
    float sq = v0*v0 + v1*v1 + v2*v2 + v3*v3;
    #pragma unroll
    for (int off = 16; off; off >>= 1) {
        s  += __shfl_xor_sync(0xffffffffu, s,  off);
        sq += __shfl_xor_sync(0xffffffffu, sq, off);
    }
    float mean = s * (1.0f / DD);
    float var  = sq * (1.0f / DD) - mean * mean;
    float rstd = rsqrtf(var + EPS);
    float4 g = ld4(gamma + lane * 4);
    float4 b = ld4(beta  + lane * 4);
    float4 o;
    o.x = (v0 - mean) * rstd * g.x + b.x;
    o.y = (v1 - mean) * rstd * g.y + b.y;
    o.z = (v2 - mean) * rstd * g.z + b.z;
    o.w = (v3 - mean) * rstd * g.w + b.w;
    long long base = (long long)row * DD + lane * 4;
    *reinterpret_cast<float4*>(g_x + base) = o;
    u32 h0, l0, h1, l1;
    split2(o.x, o.y, h0, l0);
    split2(o.z, o.w, h1, l1);
    *reinterpret_cast<uint2*>(g_xh + base) = make_uint2(h0, h1);
    *reinterpret_cast<uint2*>(g_xl + base) = make_uint2(l0, l1);
}

// ---------------- zero the aggregation buffer (covers padding) --------------
__global__ void __launch_bounds__(256) zero_agg_kernel()
{
    long long i = (long long)blockIdx.x * 256 + threadIdx.x;   // NP*DD/4 iters
    reinterpret_cast<float4*>(g_agg)[i] = make_float4(0.f, 0.f, 0.f, 0.f);
}

// ---------------- edge scatter-add (warp per edge, vector red) ---------------
__global__ void __launch_bounds__(256) scatter_kernel(const int* __restrict__ edge)
{
    int e = (int)((blockIdx.x * 256u + threadIdx.x) >> 5);
    if (e >= EE) return;
    int lane = threadIdx.x & 31;
    int src = __ldg(edge + e);
    int dst = __ldg(edge + EE + e);
    float4 v = ld4(g_x + (long long)src * DD + lane * 4);
    float* p = g_agg + (long long)dst * DD + lane * 4;
    asm volatile("red.global.add.v4.f32 [%0], {%1, %2, %3, %4};"
                 :: "l"(p), "f"(v.x), "f"(v.y), "f"(v.z), "f"(v.w)
                 : "memory");
}

// ---------------- split agg fp32 -> bf16 hi/lo ------------------------------
__global__ void __launch_bounds__(256) split_agg_kernel()
{
    long long i = (long long)blockIdx.x * 256 + threadIdx.x;   // NP*DD/4 iters
    float4 v = reinterpret_cast<const float4*>(g_agg)[i];
    u32 h0, l0, h1, l1;
    split2(v.x, v.y, h0, l0);
    split2(v.z, v.w, h1, l1);
    reinterpret_cast<uint2*>(g_ah)[i] = make_uint2(h0, h1);
    reinterpret_cast<uint2*>(g_al)[i] = make_uint2(l0, l1);
}

// ---------------- tensor-core dual GEMM + bias + ReLU + residual + LN --------
// Block: 128 rows x 128 cols, 8 warps. Warp w owns rows [w*16, w*16+16).
// bf16 split: agg@Wl ~ AhWh + AlWh + AhWl; same for x@Wr. fp32 accum.
// Dynamic smem: 8 matrices x [128 rows][40 halves] (k-chunk 32, pad 8) = 80 KB.
__global__ void __launch_bounds__(256) sage_mma_kernel(
    const float* __restrict__ bl, const float* __restrict__ gamma,
    const float* __restrict__ beta, int layer, float* __restrict__ out_opt)
{
    extern __shared__ __align__(16) __nv_bfloat16 smem[];

    int tid  = threadIdx.x;
    int w    = tid >> 5;
    int lane = tid & 31;
    int g    = lane >> 2;        // 0..7 group (row within 8)
    int c    = lane & 3;         // 0..3 (k/n sub index)
    int row0 = blockIdx.x * 128;
    long long woff = (long long)layer * DD * DD;

    float acc[16][4];
    #pragma unroll
    for (int t = 0; t < 16; t++)
        #pragma unroll
        for (int j = 0; j < 4; j++) acc[t][j] = 0.f;

    for (int kc = 0; kc < 4; kc++) {
        int k0 = kc * 32;
        const __nv_bfloat16* srcs[8];
        srcs[0] = g_ah + (long long)row0 * DD + k0;
        srcs[1] = g_al + (long long)row0 * DD + k0;
        srcs[2] = g_xh + (long long)row0 * DD + k0;
        srcs[3] = g_xl + (long long)row0 * DD + k0;
        srcs[4] = g_Wlh + woff + k0;
        srcs[5] = g_Wll + woff + k0;
        srcs[6] = g_Wrh + woff + k0;
        srcs[7] = g_Wrl + woff + k0;
        #pragma unroll
        for (int m = 0; m < 8; m++) {
            const uint4* s = reinterpret_cast<const uint4*>(srcs[m]);  // row = 16 uint4
            uint4* d = reinterpret_cast<uint4*>(smem + m * 5120);      // row = 5 uint4 (80B)
            #pragma unroll
            for (int i = tid; i < 512; i += 256) {
                int r = i >> 2, cc = i & 3;
                d[r * 5 + cc] = s[r * 16 + cc];
            }
        }
        __syncthreads();

        const u32* SA = reinterpret_cast<const u32*>(smem);  // 2560 words per matrix
        #pragma unroll
        for (int ks = 0; ks < 2; ks++) {
            int kw = ks * 8;                               // word offset (16 halves)
            int r1w = (w * 16 + g) * 20 + kw + c;
            u32 Ah[4], Al[4], Xh[4], Xl[4];
            {
                const u32* P = SA + 0 * 2560 + r1w;
                Ah[0] = P[0]; Ah[1] = P[160]; Ah[2] = P[4]; Ah[3] = P[164];
            }
            {
                const u32* P = SA + 1 * 2560 + r1w;
                Al[0] = P[0]; Al[1] = P[160]; Al[2] = P[4]; Al[3] = P[164];
            }
            {
                const u32* P = SA + 2 * 2560 + r1w;
                Xh[0] = P[0]; Xh[1] = P[160]; Xh[2] = P[4]; Xh[3] = P[164];
            }
            {
                const u32* P = SA + 3 * 2560 + r1w;
                Xl[0] = P[0]; Xl[1] = P[160]; Xl[2] = P[4]; Xl[3] = P[164];
            }
            int bw = g * 20 + kw + c;
            #pragma unroll
            for (int t = 0; t < 16; t++) {
                int b0 = bw + t * 160;
                u32 wlh[2] = { SA[4 * 2560 + b0], SA[4 * 2560 + b0 + 4] };
                u32 wll[2] = { SA[5 * 2560 + b0], SA[5 * 2560 + b0 + 4] };
                u32 wrh[2] = { SA[6 * 2560 + b0], SA[6 * 2560 + b0 + 4] };
                u32 wrl[2] = { SA[7 * 2560 + b0], SA[7 * 2560 + b0 + 4] };
                mma16816(acc[t], Ah, wlh);
                mma16816(acc[t], Al, wlh);
                mma16816(acc[t], Ah, wll);
                mma16816(acc[t], Xh, wrh);
                mma16816(acc[t], Xl, wrh);
                mma16816(acc[t], Xh, wrl);
            }
        }
        __syncthreads();
    }

    // ---- epilogue: bias + relu + residual + LayerNorm ----
    int r1 = row0 + w * 16 + g;
    int r2 = r1 + 8;
    float v[16][4];
    #pragma unroll
    for (int t = 0; t < 16; t++) {
        int col = t * 8 + c * 2;
        float2 bb = *reinterpret_cast<const float2*>(bl + col);
        float2 xa = *reinterpret_cast<const float2*>(g_x + (long long)r1 * DD + col);
        float2 xb = *reinterpret_cast<const float2*>(g_x + (long long)r2 * DD + col);
        v[t][0] = fmaxf(acc[t][0] + bb.x, 0.f) + xa.x;
        v[t][1] = fmaxf(acc[t][1] + bb.y, 0.f) + xa.y;
        v[t][2] = fmaxf(acc[t][2] + bb.x, 0.f) + xb.x;
        v[t][3] = fmaxf(acc[t][3] + bb.y, 0.f) + xb.y;
    }
    float s1 = 0.f, q1 = 0.f, s2 = 0.f, q2 = 0.f;
    #pragma unroll
    for (int t = 0; t < 16; t++) {
        s1 += v[t][0] + v[t][1];
        q1 += v[t][0] * v[t][0] + v[t][1] * v[t][1];
        s2 += v[t][2] + v[t][3];
        q2 += v[t][2] * v[t][2] + v[t][3] * v[t][3];
    }
    #pragma unroll
    for (int m = 1; m <= 2; m <<= 1) {
        s1 += __shfl_xor_sync(0xffffffffu, s1, m);
        q1 += __shfl_xor_sync(0xffffffffu, q1, m);
        s2 += __shfl_xor_sync(0xffffffffu, s2, m);
        q2 += __shfl_xor_sync(0xffffffffu, q2, m);
    }
    float mean1 = s1 * (1.0f / DD);
    float var1  = q1 * (1.0f / DD) - mean1 * mean1;
    float rs1   = rsqrtf(var1 + EPS);
    float mean2 = s2 * (1.0f / DD);
    float var2  = q2 * (1.0f / DD) - mean2 * mean2;
    float rs2   = rsqrtf(var2 + EPS);

    bool final = (out_opt != nullptr);
    #pragma unroll
    for (int t = 0; t < 16; t++) {
        int col = t * 8 + c * 2;
        float2 gg = *reinterpret_cast<const float2*>(gamma + col);
        float2 be = *reinterpret_cast<const float2*>(beta + col);
        float2 o1, o2;
        o1.x = (v[t][0] - mean1) * rs1 * gg.x + be.x;
        o1.y = (v[t][1] - mean1) * rs1 * gg.y + be.y;
        o2.x = (v[t][2] - mean2) * rs2 * gg.x + be.x;
        o2.y = (v[t][3] - mean2) * rs2 * gg.y + be.y;
        if (final) {
            if (r1 < NN)
                *reinterpret_cast<float2*>(out_opt + (long long)r1 * DD + col) = o1;
            if (r2 < NN)
                *reinterpret_cast<float2*>(out_opt + (long long)r2 * DD + col) = o2;
        } else {
            *reinterpret_cast<float2*>(g_x + (long long)r1 * DD + col) = o1;
            *reinterpret_cast<float2*>(g_x + (long long)r2 * DD + col) = o2;
            u32 h, l;
            split2(o1.x, o1.y, h, l);
            *reinterpret_cast<u32*>(g_xh + (long long)r1 * DD + col) = h;
            *reinterpret_cast<u32*>(g_xl + (long long)r1 * DD + col) = l;
            split2(o2.x, o2.y, h, l);
            *reinterpret_cast<u32*>(g_xh + (long long)r2 * DD + col) = h;
            *reinterpret_cast<u32*>(g_xl + (long long)r2 * DD + col) = l;
        }
    }
}

extern "C" void kernel_launch(void* const* d_in, const int* in_sizes, int n_in,
                              void* d_out, int out_size)
{
    const float* node_emb  = (const float*)d_in[0];
    const int*   pos       = (const int*)  d_in[1];
    const int*   edge      = (const int*)  d_in[2];
    const float* pos_table = (const float*)d_in[3];
    const float* Wl        = (const float*)d_in[4];
    const float* bl        = (const float*)d_in[5];
    const float* Wr        = (const float*)d_in[6];
    const float* emb_g     = (const float*)d_in[7];
    const float* emb_b     = (const float*)d_in[8];
    const float* hid_g     = (const float*)d_in[9];
    const float* hid_b     = (const float*)d_in[10];
    float* out = (float*)d_out;

    const int SMEM = 8 * 5120 * 2;  // 81920 bytes
    cudaFuncSetAttribute(sage_mma_kernel,
                         cudaFuncAttributeMaxDynamicSharedMemorySize, SMEM);

    pad_zero_kernel<<<88, 256>>>();
    split_w_kernel<<<192, 256>>>(Wl, Wr);
    embed_ln_kernel<<<NN / 8, 256>>>(node_emb, pos, pos_table, emb_g, emb_b);

    const int ew_grid   = NP * DD / 4 / 256;  // 6272
    const int scat_grid = EE / 8;             // 100000
    const int gemm_grid = (NN + 127) / 128;   // 391

    for (int l = 0; l < 3; l++) {
        zero_agg_kernel<<<ew_grid, 256>>>();
        scatter_kernel<<<scat_grid, 256>>>(edge);
        split_agg_kernel<<<ew_grid, 256>>>();
        float* outp = (l == 2) ? out : nullptr;
        sage_mma_kernel<<<gemm_grid, 256, SMEM>>>(
            bl + l * DD, hid_g + l * DD, hid_b + l * DD, l, outp);
    }
}

// round 4
// speedup vs baseline: 1.5346x; 1.3215x over previous
#include <cuda_runtime.h>
#include <cuda_bf16.h>

#define NN 50000
#define NP 50176          // padded rows (392*128)
#define EE 800000
#define DD 128
#define EPS 1e-5f
#define SQRTD 11.313708498984761f

typedef unsigned int u32;

__device__ float g_x[(long long)NP * DD];
__device__ __nv_bfloat16 g_xh[(long long)NP * DD];
__device__ __nv_bfloat16 g_xl[(long long)NP * DD];
__device__ __nv_bfloat16 g_ah[(long long)NP * DD];
__device__ __nv_bfloat16 g_al[(long long)NP * DD];
// weights, split + transposed: [layer][n][k]
__device__ __nv_bfloat16 g_Wlh[3 * DD * DD];
__device__ __nv_bfloat16 g_Wll[3 * DD * DD];
__device__ __nv_bfloat16 g_Wrh[3 * DD * DD];
__device__ __nv_bfloat16 g_Wrl[3 * DD * DD];
// CSR (by dst)
__device__ int g_cnt[NN];
__device__ int g_rowptr[NN + 1];
__device__ int g_cursor[NN];
__device__ int g_esrc[EE];

__device__ __forceinline__ float4 ld4(const float* __restrict__ p) {
    return *reinterpret_cast<const float4*>(p);
}

__device__ __forceinline__ void split2(float a, float b, u32& hi, u32& lo) {
    __nv_bfloat162 h = __floats2bfloat162_rn(a, b);
    float ra = a - __bfloat162float(h.x);
    float rb = b - __bfloat162float(h.y);
    __nv_bfloat162 l = __floats2bfloat162_rn(ra, rb);
    hi = *reinterpret_cast<u32*>(&h);
    lo = *reinterpret_cast<u32*>(&l);
}

__device__ __forceinline__ void mma16816(float* d, const u32* a, const u32* b) {
    asm volatile(
        "mma.sync.aligned.m16n8k16.row.col.f32.bf16.bf16.f32 "
        "{%0,%1,%2,%3}, {%4,%5,%6,%7}, {%8,%9}, {%0,%1,%2,%3};"
        : "+f"(d[0]), "+f"(d[1]), "+f"(d[2]), "+f"(d[3])
        : "r"(a[0]), "r"(a[1]), "r"(a[2]), "r"(a[3]), "r"(b[0]), "r"(b[1]));
}

// ---------------- CSR build ----------------
__global__ void __launch_bounds__(256) zero_cnt_kernel()
{
    int i = blockIdx.x * 256 + threadIdx.x;
    if (i < NN) g_cnt[i] = 0;
}

__global__ void __launch_bounds__(256) hist_kernel(const int* __restrict__ edge)
{
    int e = blockIdx.x * 256 + threadIdx.x;
    if (e >= EE) return;
    atomicAdd(&g_cnt[__ldg(edge + EE + e)], 1);
}

__global__ void __launch_bounds__(1024) scan_kernel()
{
    __shared__ int part[1024];
    int t = threadIdx.x;
    int base = t * 49;
    int s = 0;
    for (int i = 0; i < 49; i++) {
        int idx = base + i;
        if (idx < NN) s += g_cnt[idx];
    }
    part[t] = s;
    __syncthreads();
    for (int off = 1; off < 1024; off <<= 1) {
        int add = (t >= off) ? part[t - off] : 0;
        __syncthreads();
        part[t] += add;
        __syncthreads();
    }
    int run = part[t] - s;   // exclusive prefix
    for (int i = 0; i < 49; i++) {
        int idx = base + i;
        if (idx < NN) {
            g_rowptr[idx] = run;
            g_cursor[idx] = run;
            run += g_cnt[idx];
        }
    }
    if (t == 1023) g_rowptr[NN] = EE;
}

__global__ void __launch_bounds__(256) fill_kernel(const int* __restrict__ edge)
{
    int e = blockIdx.x * 256 + threadIdx.x;
    if (e >= EE) return;
    int src = __ldg(edge + e);
    int dst = __ldg(edge + EE + e);
    int slot = atomicAdd(&g_cursor[dst], 1);
    g_esrc[slot] = src;
}

// ---------------- gather aggregation + bf16 split (warp per node) -----------
__global__ void __launch_bounds__(256) gather_kernel()
{
    int node = blockIdx.x * 8 + (threadIdx.x >> 5);
    int lane = threadIdx.x & 31;
    int start = __ldg(g_rowptr + node);
    int end   = __ldg(g_rowptr + node + 1);
    float4 a = make_float4(0.f, 0.f, 0.f, 0.f);
    int i = start;
    for (; i + 1 < end; i += 2) {
        int s0 = __ldg(g_esrc + i);
        int s1 = __ldg(g_esrc + i + 1);
        float4 v0 = ld4(g_x + (long long)s0 * DD + lane * 4);
        float4 v1 = ld4(g_x + (long long)s1 * DD + lane * 4);
        a.x += v0.x; a.y += v0.y; a.z += v0.z; a.w += v0.w;
        a.x += v1.x; a.y += v1.y; a.z += v1.z; a.w += v1.w;
    }
    if (i < end) {
        int s0 = __ldg(g_esrc + i);
        float4 v0 = ld4(g_x + (long long)s0 * DD + lane * 4);
        a.x += v0.x; a.y += v0.y; a.z += v0.z; a.w += v0.w;
    }
    u32 h0, l0, h1, l1;
    split2(a.x, a.y, h0, l0);
    split2(a.z, a.w, h1, l1);
    long long base = (long long)node * DD + lane * 4;
    *reinterpret_cast<uint2*>(g_ah + base) = make_uint2(h0, h1);
    *reinterpret_cast<uint2*>(g_al + base) = make_uint2(l0, l1);
}

// ---------------- weight split + transpose (runs once per launch) ------------
__global__ void __launch_bounds__(256) split_w_kernel(
    const float* __restrict__ Wl, const float* __restrict__ Wr)
{
    int idx = blockIdx.x * 256 + threadIdx.x;       // 3*128*128 = 49152
    if (idx >= 3 * DD * DD) return;
    int l = idx / (DD * DD);
    int k = (idx / DD) % DD;
    int n = idx % DD;
    int dst = l * DD * DD + n * DD + k;             // transposed [l][n][k]
    float wl = Wl[idx];
    __nv_bfloat16 h = __float2bfloat16(wl);
    g_Wlh[dst] = h;
    g_Wll[dst] = __float2bfloat16(wl - __bfloat162float(h));
    float wr = Wr[idx];
    __nv_bfloat16 h2 = __float2bfloat16(wr);
    g_Wrh[dst] = h2;
    g_Wrl[dst] = __float2bfloat16(wr - __bfloat162float(h2));
}

// ---------------- zero padding rows of buffers (once per launch) -------------
__global__ void __launch_bounds__(256) pad_zero_kernel()
{
    int i = blockIdx.x * 256 + threadIdx.x;         // (NP-NN)*128 = 22528
    if (i >= (NP - NN) * DD) return;
    long long off = (long long)NN * DD + i;
    g_x[off] = 0.f;
    __nv_bfloat16 z = __float2bfloat16(0.f);
    g_xh[off] = z;
    g_xl[off] = z;
    g_ah[off] = z;
    g_al[off] = z;
}

// ---------------- embedding + LayerNorm (writes fp32 + bf16 hi/lo) ----------
__global__ void __launch_bounds__(256) embed_ln_kernel(
    const float* __restrict__ node_emb, const int* __restrict__ pos,
    const float* __restrict__ pos_table, const float* __restrict__ gamma,
    const float* __restrict__ beta)
{
    int row  = blockIdx.x * 8 + (threadIdx.x >> 5);
    int lane = threadIdx.x & 31;
    int p = __ldg(pos + row);
    float4 a  = ld4(node_emb + (long long)row * DD + lane * 4);
    float4 pe = ld4(pos_table + (long long)p * DD + lane * 4);
    float v0 = a.x * SQRTD + pe.x;
    float v1 = a.y * SQRTD + pe.y;
    float v2 = a.z * SQRTD + pe.z;
    float v3 = a.w * SQRTD + pe.w;
    float s  = v0 + v1 + v2 + v3;
    float sq = v0*v0 + v1*v1 + v2*v2 + v3*v3;
    #pragma unroll
    for (int off = 16; off; off >>= 1) {
        s  += __shfl_xor_sync(0xffffffffu, s,  off);
        sq += __shfl_xor_sync(0xffffffffu, sq, off);
    }
    float mean = s * (1.0f / DD);
    float var  = sq * (1.0f / DD) - mean * mean;
    float rstd = rsqrtf(var + EPS);
    float4 g = ld4(gamma + lane * 4);
    float4 b = ld4(beta  + lane * 4);
    float4 o;
    o.x = (v0 - mean) * rstd * g.x + b.x;
    o.y = (v1 - mean) * rstd * g.y + b.y;
    o.z = (v2 - mean) * rstd * g.z + b.z;
    o.w = (v3 - mean) * rstd * g.w + b.w;
    long long base = (long long)row * DD + lane * 4;
    *reinterpret_cast<float4*>(g_x + base) = o;
    u32 h0, l0, h1, l1;
    split2(o.x, o.y, h0, l0);
    split2(o.z, o.w, h1, l1);
    *reinterpret_cast<uint2*>(g_xh + base) = make_uint2(h0, h1);
    *reinterpret_cast<uint2*>(g_xl + base) = make_uint2(l0, l1);
}

// ---------------- tensor-core dual GEMM + bias + ReLU + residual + LN --------
// Block: 128 rows x 128 cols, 8 warps. Warp w owns rows [w*16, w*16+16).
// bf16 split: agg@Wl ~ AhWh + AlWh + AhWl; same for x@Wr. fp32 accum.
// Dynamic smem: 8 matrices x [128 rows][40 halves] (k-chunk 32, pad 8) = 80 KB.
__global__ void __launch_bounds__(256) sage_mma_kernel(
    const float* __restrict__ bl, const float* __restrict__ gamma,
    const float* __restrict__ beta, int layer, float* __restrict__ out_opt)
{
    extern __shared__ __align__(16) __nv_bfloat16 smem[];

    int tid  = threadIdx.x;
    int w    = tid >> 5;
    int lane = tid & 31;
    int g    = lane >> 2;        // 0..7 group (row within 8)
    int c    = lane & 3;         // 0..3 (k/n sub index)
    int row0 = blockIdx.x * 128;
    long long woff = (long long)layer * DD * DD;

    float acc[16][4];
    #pragma unroll
    for (int t = 0; t < 16; t++)
        #pragma unroll
        for (int j = 0; j < 4; j++) acc[t][j] = 0.f;

    for (int kc = 0; kc < 4; kc++) {
        int k0 = kc * 32;
        const __nv_bfloat16* srcs[8];
        srcs[0] = g_ah + (long long)row0 * DD + k0;
        srcs[1] = g_al + (long long)row0 * DD + k0;
        srcs[2] = g_xh + (long long)row0 * DD + k0;
        srcs[3] = g_xl + (long long)row0 * DD + k0;
        srcs[4] = g_Wlh + woff + k0;
        srcs[5] = g_Wll + woff + k0;
        srcs[6] = g_Wrh + woff + k0;
        srcs[7] = g_Wrl + woff + k0;
        #pragma unroll
        for (int m = 0; m < 8; m++) {
            const uint4* s = reinterpret_cast<const uint4*>(srcs[m]);  // row = 16 uint4
            uint4* d = reinterpret_cast<uint4*>(smem + m * 5120);      // row = 5 uint4 (80B)
            #pragma unroll
            for (int i = tid; i < 512; i += 256) {
                int r = i >> 2, cc = i & 3;
                d[r * 5 + cc] = s[r * 16 + cc];
            }
        }
        __syncthreads();

        const u32* SA = reinterpret_cast<const u32*>(smem);  // 2560 words per matrix
        #pragma unroll
        for (int ks = 0; ks < 2; ks++) {
            int kw = ks * 8;                               // word offset (16 halves)
            int r1w = (w * 16 + g) * 20 + kw + c;
            u32 Ah[4], Al[4], Xh[4], Xl[4];
            {
                const u32* P = SA + 0 * 2560 + r1w;
                Ah[0] = P[0]; Ah[1] = P[160]; Ah[2] = P[4]; Ah[3] = P[164];
            }
            {
                const u32* P = SA + 1 * 2560 + r1w;
                Al[0] = P[0]; Al[1] = P[160]; Al[2] = P[4]; Al[3] = P[164];
            }
            {
                const u32* P = SA + 2 * 2560 + r1w;
                Xh[0] = P[0]; Xh[1] = P[160]; Xh[2] = P[4]; Xh[3] = P[164];
            }
            {
                const u32* P = SA + 3 * 2560 + r1w;
                Xl[0] = P[0]; Xl[1] = P[160]; Xl[2] = P[4]; Xl[3] = P[164];
            }
            int bw = g * 20 + kw + c;
            #pragma unroll
            for (int t = 0; t < 16; t++) {
                int b0 = bw + t * 160;
                u32 wlh[2] = { SA[4 * 2560 + b0], SA[4 * 2560 + b0 + 4] };
                u32 wll[2] = { SA[5 * 2560 + b0], SA[5 * 2560 + b0 + 4] };
                u32 wrh[2] = { SA[6 * 2560 + b0], SA[6 * 2560 + b0 + 4] };
                u32 wrl[2] = { SA[7 * 2560 + b0], SA[7 * 2560 + b0 + 4] };
                mma16816(acc[t], Ah, wlh);
                mma16816(acc[t], Al, wlh);
                mma16816(acc[t], Ah, wll);
                mma16816(acc[t], Xh, wrh);
                mma16816(acc[t], Xl, wrh);
                mma16816(acc[t], Xh, wrl);
            }
        }
        __syncthreads();
    }

    // ---- epilogue: bias + relu + residual + LayerNorm ----
    int r1 = row0 + w * 16 + g;
    int r2 = r1 + 8;
    float v[16][4];
    #pragma unroll
    for (int t = 0; t < 16; t++) {
        int col = t * 8 + c * 2;
        float2 bb = *reinterpret_cast<const float2*>(bl + col);
        float2 xa = *reinterpret_cast<const float2*>(g_x + (long long)r1 * DD + col);
        float2 xb = *reinterpret_cast<const float2*>(g_x + (long long)r2 * DD + col);
        v[t][0] = fmaxf(acc[t][0] + bb.x, 0.f) + xa.x;
        v[t][1] = fmaxf(acc[t][1] + bb.y, 0.f) + xa.y;
        v[t][2] = fmaxf(acc[t][2] + bb.x, 0.f) + xb.x;
        v[t][3] = fmaxf(acc[t][3] + bb.y, 0.f) + xb.y;
    }
    float s1 = 0.f, q1 = 0.f, s2 = 0.f, q2 = 0.f;
    #pragma unroll
    for (int t = 0; t < 16; t++) {
        s1 += v[t][0] + v[t][1];
        q1 += v[t][0] * v[t][0] + v[t][1] * v[t][1];
        s2 += v[t][2] + v[t][3];
        q2 += v[t][2] * v[t][2] + v[t][3] * v[t][3];
    }
    #pragma unroll
    for (int m = 1; m <= 2; m <<= 1) {
        s1 += __shfl_xor_sync(0xffffffffu, s1, m);
        q1 += __shfl_xor_sync(0xffffffffu, q1, m);
        s2 += __shfl_xor_sync(0xffffffffu, s2, m);
        q2 += __shfl_xor_sync(0xffffffffu, q2, m);
    }
    float mean1 = s1 * (1.0f / DD);
    float var1  = q1 * (1.0f / DD) - mean1 * mean1;
    float rs1   = rsqrtf(var1 + EPS);
    float mean2 = s2 * (1.0f / DD);
    float var2  = q2 * (1.0f / DD) - mean2 * mean2;
    float rs2   = rsqrtf(var2 + EPS);

    bool final = (out_opt != nullptr);
    #pragma unroll
    for (int t = 0; t < 16; t++) {
        int col = t * 8 + c * 2;
        float2 gg = *reinterpret_cast<const float2*>(gamma + col);
        float2 be = *reinterpret_cast<const float2*>(beta + col);
        float2 o1, o2;
        o1.x = (v[t][0] - mean1) * rs1 * gg.x + be.x;
        o1.y = (v[t][1] - mean1) * rs1 * gg.y + be.y;
        o2.x = (v[t][2] - mean2) * rs2 * gg.x + be.x;
        o2.y = (v[t][3] - mean2) * rs2 * gg.y + be.y;
        if (final) {
            if (r1 < NN)
                *reinterpret_cast<float2*>(out_opt + (long long)r1 * DD + col) = o1;
            if (r2 < NN)
                *reinterpret_cast<float2*>(out_opt + (long long)r2 * DD + col) = o2;
        } else {
            *reinterpret_cast<float2*>(g_x + (long long)r1 * DD + col) = o1;
            *reinterpret_cast<float2*>(g_x + (long long)r2 * DD + col) = o2;
            u32 h, l;
            split2(o1.x, o1.y, h, l);
            *reinterpret_cast<u32*>(g_xh + (long long)r1 * DD + col) = h;
            *reinterpret_cast<u32*>(g_xl + (long long)r1 * DD + col) = l;
            split2(o2.x, o2.y, h, l);
            *reinterpret_cast<u32*>(g_xh + (long long)r2 * DD + col) = h;
            *reinterpret_cast<u32*>(g_xl + (long long)r2 * DD + col) = l;
        }
    }
}

extern "C" void kernel_launch(void* const* d_in, const int* in_sizes, int n_in,
                              void* d_out, int out_size)
{
    const float* node_emb  = (const float*)d_in[0];
    const int*   pos       = (const int*)  d_in[1];
    const int*   edge      = (const int*)  d_in[2];
    const float* pos_table = (const float*)d_in[3];
    const float* Wl        = (const float*)d_in[4];
    const float* bl        = (const float*)d_in[5];
    const float* Wr        = (const float*)d_in[6];
    const float* emb_g     = (const float*)d_in[7];
    const float* emb_b     = (const float*)d_in[8];
    const float* hid_g     = (const float*)d_in[9];
    const float* hid_b     = (const float*)d_in[10];
    float* out = (float*)d_out;

    const int SMEM = 8 * 5120 * 2;  // 81920 bytes
    cudaFuncSetAttribute(sage_mma_kernel,
                         cudaFuncAttributeMaxDynamicSharedMemorySize, SMEM);

    // CSR build (once per launch)
    zero_cnt_kernel<<<196, 256>>>();
    hist_kernel<<<3125, 256>>>(edge);
    scan_kernel<<<1, 1024>>>();
    fill_kernel<<<3125, 256>>>(edge);

    pad_zero_kernel<<<88, 256>>>();
    split_w_kernel<<<192, 256>>>(Wl, Wr);
    embed_ln_kernel<<<NN / 8, 256>>>(node_emb, pos, pos_table, emb_g, emb_b);

    const int gath_grid = NN / 8;             // 6250
    const int gemm_grid = (NN + 127) / 128;   // 391

    for (int l = 0; l < 3; l++) {
        gather_kernel<<<gath_grid, 256>>>();
        float* outp = (l == 2) ? out : nullptr;
        sage_mma_kernel<<<gemm_grid, 256, SMEM>>>(
            bl + l * DD, hid_g + l * DD, hid_b + l * DD, l, outp);
    }
}

// round 5
// speedup vs baseline: 1.6384x; 1.0676x over previous
#include <cuda_runtime.h>
#include <cuda_bf16.h>

#define NN 50000
#define NP 50176          // padded rows (392*128)
#define EE 800000
#define DD 128
#define EPS 1e-5f
#define SQRTD 11.313708498984761f

typedef unsigned int u32;

__device__ __align__(16) float g_x[(long long)NP * DD];
__device__ __align__(16) __nv_bfloat16 g_xh[(long long)NP * DD];
__device__ __align__(16) __nv_bfloat16 g_xl[(long long)NP * DD];
__device__ __align__(16) __nv_bfloat16 g_ah[(long long)NP * DD];
__device__ __align__(16) __nv_bfloat16 g_al[(long long)NP * DD];
// weights, split + transposed: [layer][n][k]
__device__ __align__(16) __nv_bfloat16 g_Wlh[3 * DD * DD];
__device__ __align__(16) __nv_bfloat16 g_Wll[3 * DD * DD];
__device__ __align__(16) __nv_bfloat16 g_Wrh[3 * DD * DD];
__device__ __align__(16) __nv_bfloat16 g_Wrl[3 * DD * DD];
// CSR (by dst)
__device__ int g_cnt[NN];
__device__ int g_rowptr[NN + 1];
__device__ int g_cursor[NN];
__device__ int g_esrc[EE];

__device__ __forceinline__ float4 ld4(const float* __restrict__ p) {
    return *reinterpret_cast<const float4*>(p);
}

__device__ __forceinline__ void split2(float a, float b, u32& hi, u32& lo) {
    __nv_bfloat162 h = __floats2bfloat162_rn(a, b);
    float ra = a - __bfloat162float(h.x);
    float rb = b - __bfloat162float(h.y);
    __nv_bfloat162 l = __floats2bfloat162_rn(ra, rb);
    hi = *reinterpret_cast<u32*>(&h);
    lo = *reinterpret_cast<u32*>(&l);
}

__device__ __forceinline__ void mma16816(float* d, const u32* a, const u32* b) {
    asm volatile(
        "mma.sync.aligned.m16n8k16.row.col.f32.bf16.bf16.f32 "
        "{%0,%1,%2,%3}, {%4,%5,%6,%7}, {%8,%9}, {%0,%1,%2,%3};"
        : "+f"(d[0]), "+f"(d[1]), "+f"(d[2]), "+f"(d[3])
        : "r"(a[0]), "r"(a[1]), "r"(a[2]), "r"(a[3]), "r"(b[0]), "r"(b[1]));
}

// ---------------- CSR build ----------------
__global__ void __launch_bounds__(256) zero_cnt_kernel()
{
    int i = blockIdx.x * 256 + threadIdx.x;
    if (i < NN) g_cnt[i] = 0;
}

__global__ void __launch_bounds__(256) hist_kernel(const int* __restrict__ edge)
{
    int i = blockIdx.x * 256 + threadIdx.x;
    if (i >= EE / 4) return;
    int4 d = __ldg(reinterpret_cast<const int4*>(edge + EE) + i);
    atomicAdd(&g_cnt[d.x], 1);
    atomicAdd(&g_cnt[d.y], 1);
    atomicAdd(&g_cnt[d.z], 1);
    atomicAdd(&g_cnt[d.w], 1);
}

__global__ void __launch_bounds__(1024) scan_kernel()
{
    __shared__ int part[1024];
    int t = threadIdx.x;
    int base = t * 49;
    int s = 0;
    for (int i = 0; i < 49; i++) {
        int idx = base + i;
        if (idx < NN) s += g_cnt[idx];
    }
    part[t] = s;
    __syncthreads();
    for (int off = 1; off < 1024; off <<= 1) {
        int add = (t >= off) ? part[t - off] : 0;
        __syncthreads();
        part[t] += add;
        __syncthreads();
    }
    int run = part[t] - s;   // exclusive prefix
    for (int i = 0; i < 49; i++) {
        int idx = base + i;
        if (idx < NN) {
            g_rowptr[idx] = run;
            g_cursor[idx] = run;
            run += g_cnt[idx];
        }
    }
    if (t == 1023) g_rowptr[NN] = EE;
}

__global__ void __launch_bounds__(256) fill_kernel(const int* __restrict__ edge)
{
    int i = blockIdx.x * 256 + threadIdx.x;
    if (i >= EE / 4) return;
    int4 s4 = __ldg(reinterpret_cast<const int4*>(edge) + i);
    int4 d4 = __ldg(reinterpret_cast<const int4*>(edge + EE) + i);
    int p0 = atomicAdd(&g_cursor[d4.x], 1);
    int p1 = atomicAdd(&g_cursor[d4.y], 1);
    int p2 = atomicAdd(&g_cursor[d4.z], 1);
    int p3 = atomicAdd(&g_cursor[d4.w], 1);
    g_esrc[p0] = s4.x;
    g_esrc[p1] = s4.y;
    g_esrc[p2] = s4.z;
    g_esrc[p3] = s4.w;
}

// ---------------- gather aggregation + bf16 split (warp per node) -----------
__global__ void __launch_bounds__(256) gather_kernel()
{
    int node = blockIdx.x * 8 + (threadIdx.x >> 5);
    int lane = threadIdx.x & 31;
    int start = __ldg(g_rowptr + node);
    int end   = __ldg(g_rowptr + node + 1);
    float4 a = make_float4(0.f, 0.f, 0.f, 0.f);
    int i = start;
    for (; i + 3 < end; i += 4) {
        int s0 = __ldg(g_esrc + i);
        int s1 = __ldg(g_esrc + i + 1);
        int s2 = __ldg(g_esrc + i + 2);
        int s3 = __ldg(g_esrc + i + 3);
        float4 v0 = ld4(g_x + (long long)s0 * DD + lane * 4);
        float4 v1 = ld4(g_x + (long long)s1 * DD + lane * 4);
        float4 v2 = ld4(g_x + (long long)s2 * DD + lane * 4);
        float4 v3 = ld4(g_x + (long long)s3 * DD + lane * 4);
        a.x += v0.x + v1.x + v2.x + v3.x;
        a.y += v0.y + v1.y + v2.y + v3.y;
        a.z += v0.z + v1.z + v2.z + v3.z;
        a.w += v0.w + v1.w + v2.w + v3.w;
    }
    for (; i < end; i++) {
        int s0 = __ldg(g_esrc + i);
        float4 v0 = ld4(g_x + (long long)s0 * DD + lane * 4);
        a.x += v0.x; a.y += v0.y; a.z += v0.z; a.w += v0.w;
    }
    u32 h0, l0, h1, l1;
    split2(a.x, a.y, h0, l0);
    split2(a.z, a.w, h1, l1);
    long long base = (long long)node * DD + lane * 4;
    *reinterpret_cast<uint2*>(g_ah + base) = make_uint2(h0, h1);
    *reinterpret_cast<uint2*>(g_al + base) = make_uint2(l0, l1);
}

// ---------------- weight split + transpose (runs once per launch) ------------
__global__ void __launch_bounds__(256) split_w_kernel(
    const float* __restrict__ Wl, const float* __restrict__ Wr)
{
    int idx = blockIdx.x * 256 + threadIdx.x;       // 3*128*128 = 49152
    if (idx >= 3 * DD * DD) return;
    int l = idx / (DD * DD);
    int k = (idx / DD) % DD;
    int n = idx % DD;
    int dst = l * DD * DD + n * DD + k;             // transposed [l][n][k]
    float wl = Wl[idx];
    __nv_bfloat16 h = __float2bfloat16(wl);
    g_Wlh[dst] = h;
    g_Wll[dst] = __float2bfloat16(wl - __bfloat162float(h));
    float wr = Wr[idx];
    __nv_bfloat16 h2 = __float2bfloat16(wr);
    g_Wrh[dst] = h2;
    g_Wrl[dst] = __float2bfloat16(wr - __bfloat162float(h2));
}

// ---------------- zero padding rows of buffers (once per launch) -------------
__global__ void __launch_bounds__(256) pad_zero_kernel()
{
    int i = blockIdx.x * 256 + threadIdx.x;         // (NP-NN)*128 = 22528
    if (i >= (NP - NN) * DD) return;
    long long off = (long long)NN * DD + i;
    g_x[off] = 0.f;
    __nv_bfloat16 z = __float2bfloat16(0.f);
    g_xh[off] = z;
    g_xl[off] = z;
    g_ah[off] = z;
    g_al[off] = z;
}

// ---------------- embedding + LayerNorm (writes fp32 + bf16 hi/lo) ----------
__global__ void __launch_bounds__(256) embed_ln_kernel(
    const float* __restrict__ node_emb, const int* __restrict__ pos,
    const float* __restrict__ pos_table, const float* __restrict__ gamma,
    const float* __restrict__ beta)
{
    int row  = blockIdx.x * 8 + (threadIdx.x >> 5);
    int lane = threadIdx.x & 31;
    int p = __ldg(pos + row);
    float4 a  = ld4(node_emb + (long long)row * DD + lane * 4);
    float4 pe = ld4(pos_table + (long long)p * DD + lane * 4);
    float v0 = a.x * SQRTD + pe.x;
    float v1 = a.y * SQRTD + pe.y;
    float v2 = a.z * SQRTD + pe.z;
    float v3 = a.w * SQRTD + pe.w;
    float s  = v0 + v1 + v2 + v3;
    float sq = v0*v0 + v1*v1 + v2*v2 + v3*v3;
    #pragma unroll
    for (int off = 16; off; off >>= 1) {
        s  += __shfl_xor_sync(0xffffffffu, s,  off);
        sq += __shfl_xor_sync(0xffffffffu, sq, off);
    }
    float mean = s * (1.0f / DD);
    float var  = sq * (1.0f / DD) - mean * mean;
    float rstd = rsqrtf(var + EPS);
    float4 g = ld4(gamma + lane * 4);
    float4 b = ld4(beta  + lane * 4);
    float4 o;
    o.x = (v0 - mean) * rstd * g.x + b.x;
    o.y = (v1 - mean) * rstd * g.y + b.y;
    o.z = (v2 - mean) * rstd * g.z + b.z;
    o.w = (v3 - mean) * rstd * g.w + b.w;
    long long base = (long long)row * DD + lane * 4;
    *reinterpret_cast<float4*>(g_x + base) = o;
    u32 h0, l0, h1, l1;
    split2(o.x, o.y, h0, l0);
    split2(o.z, o.w, h1, l1);
    *reinterpret_cast<uint2*>(g_xh + base) = make_uint2(h0, h1);
    *reinterpret_cast<uint2*>(g_xl + base) = make_uint2(l0, l1);
}

// ---------------- tensor-core dual GEMM + bias + ReLU + residual + LN --------
// Weights persistent in smem (4 matrices, 128 rows x 68-word padded stride,
// bank-conflict-free B frags). A fragments loaded directly from global (L2-hot).
// Block: 128 rows x 128 cols, 8 warps; warp w owns rows [w*16, w*16+16).
__global__ void __launch_bounds__(256) sage_mma_kernel(
    const float* __restrict__ bl, const float* __restrict__ gamma,
    const float* __restrict__ beta, int layer, float* __restrict__ out_opt)
{
    extern __shared__ __align__(16) u32 smem[];   // 4 * 8704 words = 136 KB

    int tid  = threadIdx.x;
    int w    = tid >> 5;
    int lane = tid & 31;
    int g    = lane >> 2;        // 0..7
    int c    = lane & 3;         // 0..3
    int row0 = blockIdx.x * 128;
    long long woff = (long long)layer * DD * DD;

    // ---- load 4 weight matrices into smem once ----
    {
        const __nv_bfloat16* wsrc[4] = { g_Wlh + woff, g_Wll + woff,
                                         g_Wrh + woff, g_Wrl + woff };
        #pragma unroll
        for (int m = 0; m < 4; m++) {
            const uint4* s = reinterpret_cast<const uint4*>(wsrc[m]);  // 16/row
            uint4* d = reinterpret_cast<uint4*>(smem) + m * 2176;      // 17/row
            for (int i = tid; i < 2048; i += 256) {
                int n = i >> 4, c4 = i & 15;
                d[n * 17 + c4] = s[i];
            }
        }
    }
    __syncthreads();

    float acc[16][4];
    #pragma unroll
    for (int t = 0; t < 16; t++)
        #pragma unroll
        for (int j = 0; j < 4; j++) acc[t][j] = 0.f;

    int r1 = row0 + w * 16 + g;
    const u32* pah = reinterpret_cast<const u32*>(g_ah) + (long long)r1 * 64;
    const u32* pal = reinterpret_cast<const u32*>(g_al) + (long long)r1 * 64;
    const u32* pxh = reinterpret_cast<const u32*>(g_xh) + (long long)r1 * 64;
    const u32* pxl = reinterpret_cast<const u32*>(g_xl) + (long long)r1 * 64;

    for (int ks = 0; ks < 8; ks++) {
        int kw = ks * 8 + c;
        u32 Ah[4] = { pah[kw], pah[512 + kw], pah[kw + 4], pah[512 + kw + 4] };
        u32 Al[4] = { pal[kw], pal[512 + kw], pal[kw + 4], pal[512 + kw + 4] };
        u32 Xh[4] = { pxh[kw], pxh[512 + kw], pxh[kw + 4], pxh[512 + kw + 4] };
        u32 Xl[4] = { pxl[kw], pxl[512 + kw], pxl[kw + 4], pxl[512 + kw + 4] };
        #pragma unroll
        for (int t = 0; t < 16; t++) {
            int b0 = (t * 8 + g) * 68 + kw;
            u32 wlh[2] = { smem[b0],         smem[b0 + 4] };
            u32 wll[2] = { smem[8704 + b0],  smem[8704 + b0 + 4] };
            u32 wrh[2] = { smem[17408 + b0], smem[17408 + b0 + 4] };
            u32 wrl[2] = { smem[26112 + b0], smem[26112 + b0 + 4] };
            mma16816(acc[t], Ah, wlh);
            mma16816(acc[t], Al, wlh);
            mma16816(acc[t], Ah, wll);
            mma16816(acc[t], Xh, wrh);
            mma16816(acc[t], Xl, wrh);
            mma16816(acc[t], Xh, wrl);
        }
    }

    // ---- epilogue: bias + relu + residual + LayerNorm ----
    int r2 = r1 + 8;
    float v[16][4];
    #pragma unroll
    for (int t = 0; t < 16; t++) {
        int col = t * 8 + c * 2;
        float2 bb = *reinterpret_cast<const float2*>(bl + col);
        float2 xa = *reinterpret_cast<const float2*>(g_x + (long long)r1 * DD + col);
        float2 xb = *reinterpret_cast<const float2*>(g_x + (long long)r2 * DD + col);
        v[t][0] = fmaxf(acc[t][0] + bb.x, 0.f) + xa.x;
        v[t][1] = fmaxf(acc[t][1] + bb.y, 0.f) + xa.y;
        v[t][2] = fmaxf(acc[t][2] + bb.x, 0.f) + xb.x;
        v[t][3] = fmaxf(acc[t][3] + bb.y, 0.f) + xb.y;
    }
    float s1 = 0.f, q1 = 0.f, s2 = 0.f, q2 = 0.f;
    #pragma unroll
    for (int t = 0; t < 16; t++) {
        s1 += v[t][0] + v[t][1];
        q1 += v[t][0] * v[t][0] + v[t][1] * v[t][1];
        s2 += v[t][2] + v[t][3];
        q2 += v[t][2] * v[t][2] + v[t][3] * v[t][3];
    }
    #pragma unroll
    for (int m = 1; m <= 2; m <<= 1) {
        s1 += __shfl_xor_sync(0xffffffffu, s1, m);
        q1 += __shfl_xor_sync(0xffffffffu, q1, m);
        s2 += __shfl_xor_sync(0xffffffffu, s2, m);
        q2 += __shfl_xor_sync(0xffffffffu, q2, m);
    }
    float mean1 = s1 * (1.0f / DD);
    float var1  = q1 * (1.0f / DD) - mean1 * mean1;
    float rs1   = rsqrtf(var1 + EPS);
    float mean2 = s2 * (1.0f / DD);
    float var2  = q2 * (1.0f / DD) - mean2 * mean2;
    float rs2   = rsqrtf(var2 + EPS);

    bool final = (out_opt != nullptr);
    #pragma unroll
    for (int t = 0; t < 16; t++) {
        int col = t * 8 + c * 2;
        float2 gg = *reinterpret_cast<const float2*>(gamma + col);
        float2 be = *reinterpret_cast<const float2*>(beta + col);
        float2 o1, o2;
        o1.x = (v[t][0] - mean1) * rs1 * gg.x + be.x;
        o1.y = (v[t][1] - mean1) * rs1 * gg.y + be.y;
        o2.x = (v[t][2] - mean2) * rs2 * gg.x + be.x;
        o2.y = (v[t][3] - mean2) * rs2 * gg.y + be.y;
        if (final) {
            if (r1 < NN)
                *reinterpret_cast<float2*>(out_opt + (long long)r1 * DD + col) = o1;
            if (r2 < NN)
                *reinterpret_cast<float2*>(out_opt + (long long)r2 * DD + col) = o2;
        } else {
            *reinterpret_cast<float2*>(g_x + (long long)r1 * DD + col) = o1;
            *reinterpret_cast<float2*>(g_x + (long long)r2 * DD + col) = o2;
            u32 h, l;
            split2(o1.x, o1.y, h, l);
            *reinterpret_cast<u32*>(g_xh + (long long)r1 * DD + col) = h;
            *reinterpret_cast<u32*>(g_xl + (long long)r1 * DD + col) = l;
            split2(o2.x, o2.y, h, l);
            *reinterpret_cast<u32*>(g_xh + (long long)r2 * DD + col) = h;
            *reinterpret_cast<u32*>(g_xl + (long long)r2 * DD + col) = l;
        }
    }
}

extern "C" void kernel_launch(void* const* d_in, const int* in_sizes, int n_in,
                              void* d_out, int out_size)
{
    const float* node_emb  = (const float*)d_in[0];
    const int*   pos       = (const int*)  d_in[1];
    const int*   edge      = (const int*)  d_in[2];
    const float* pos_table = (const float*)d_in[3];
    const float* Wl        = (const float*)d_in[4];
    const float* bl        = (const float*)d_in[5];
    const float* Wr        = (const float*)d_in[6];
    const float* emb_g     = (const float*)d_in[7];
    const float* emb_b     = (const float*)d_in[8];
    const float* hid_g     = (const float*)d_in[9];
    const float* hid_b     = (const float*)d_in[10];
    float* out = (float*)d_out;

    const int SMEM = 4 * 8704 * 4;  // 139264 bytes
    cudaFuncSetAttribute(sage_mma_kernel,
                         cudaFuncAttributeMaxDynamicSharedMemorySize, SMEM);

    // CSR build (once per launch)
    zero_cnt_kernel<<<196, 256>>>();
    hist_kernel<<<(EE / 4 + 255) / 256, 256>>>(edge);
    scan_kernel<<<1, 1024>>>();
    fill_kernel<<<(EE / 4 + 255) / 256, 256>>>(edge);

    pad_zero_kernel<<<88, 256>>>();
    split_w_kernel<<<192, 256>>>(Wl, Wr);
    embed_ln_kernel<<<NN / 8, 256>>>(node_emb, pos, pos_table, emb_g, emb_b);

    const int gath_grid = NN / 8;             // 6250
    const int gemm_grid = (NN + 127) / 128;   // 391

    for (int l = 0; l < 3; l++) {
        gather_kernel<<<gath_grid, 256>>>();
        float* outp = (l == 2) ? out : nullptr;
        sage_mma_kernel<<<gemm_grid, 256, SMEM>>>(
            bl + l * DD, hid_g + l * DD, hid_b + l * DD, l, outp);
    }
}

// round 6
// speedup vs baseline: 1.7375x; 1.0605x over previous
#include <cuda_runtime.h>
#include <cuda_bf16.h>

#define NN 50000
#define NP 50304          // padded rows (262*192)
#define EE 800000
#define DD 128
#define EPS 1e-5f
#define SQRTD 11.313708498984761f

typedef unsigned int u32;

__device__ __align__(16) float g_x[(long long)NP * DD];
__device__ __align__(16) __nv_bfloat16 g_xh[(long long)NP * DD];
__device__ __align__(16) __nv_bfloat16 g_xl[(long long)NP * DD];
__device__ __align__(16) __nv_bfloat16 g_ah[(long long)NP * DD];
__device__ __align__(16) __nv_bfloat16 g_al[(long long)NP * DD];
// weights, split + transposed: [layer][n][k]
__device__ __align__(16) __nv_bfloat16 g_Wlh[3 * DD * DD];
__device__ __align__(16) __nv_bfloat16 g_Wll[3 * DD * DD];
__device__ __align__(16) __nv_bfloat16 g_Wrh[3 * DD * DD];
__device__ __align__(16) __nv_bfloat16 g_Wrl[3 * DD * DD];
// CSR (by dst)
__device__ int g_cnt[NN];
__device__ int g_rowptr[NN + 1];
__device__ __align__(16) int g_eoff[EE];
__device__ int g_esrc[EE];

__device__ __forceinline__ float4 ld4(const float* __restrict__ p) {
    return *reinterpret_cast<const float4*>(p);
}

__device__ __forceinline__ void split2(float a, float b, u32& hi, u32& lo) {
    __nv_bfloat162 h = __floats2bfloat162_rn(a, b);
    float ra = a - __bfloat162float(h.x);
    float rb = b - __bfloat162float(h.y);
    __nv_bfloat162 l = __floats2bfloat162_rn(ra, rb);
    hi = *reinterpret_cast<u32*>(&h);
    lo = *reinterpret_cast<u32*>(&l);
}

__device__ __forceinline__ void mma16816(float* d, const u32* a, const u32* b) {
    asm volatile(
        "mma.sync.aligned.m16n8k16.row.col.f32.bf16.bf16.f32 "
        "{%0,%1,%2,%3}, {%4,%5,%6,%7}, {%8,%9}, {%0,%1,%2,%3};"
        : "+f"(d[0]), "+f"(d[1]), "+f"(d[2]), "+f"(d[3])
        : "r"(a[0]), "r"(a[1]), "r"(a[2]), "r"(a[3]), "r"(b[0]), "r"(b[1]));
}

// ---------------- CSR build ----------------
__global__ void __launch_bounds__(256) zero_cnt_kernel()
{
    int i = blockIdx.x * 256 + threadIdx.x;
    if (i < NN) g_cnt[i] = 0;
}

// single pass: count + record per-edge slot offset
__global__ void __launch_bounds__(256) hist_off_kernel(const int* __restrict__ edge)
{
    int i = blockIdx.x * 256 + threadIdx.x;
    if (i >= EE / 4) return;
    int4 d = __ldg(reinterpret_cast<const int4*>(edge + EE) + i);
    int o0 = atomicAdd(&g_cnt[d.x], 1);
    int o1 = atomicAdd(&g_cnt[d.y], 1);
    int o2 = atomicAdd(&g_cnt[d.z], 1);
    int o3 = atomicAdd(&g_cnt[d.w], 1);
    reinterpret_cast<int4*>(g_eoff)[i] = make_int4(o0, o1, o2, o3);
}

__global__ void __launch_bounds__(1024) scan_kernel()
{
    __shared__ int part[1024];
    int t = threadIdx.x;
    int base = t * 49;
    int s = 0;
    for (int i = 0; i < 49; i++) {
        int idx = base + i;
        if (idx < NN) s += g_cnt[idx];
    }
    part[t] = s;
    __syncthreads();
    for (int off = 1; off < 1024; off <<= 1) {
        int add = (t >= off) ? part[t - off] : 0;
        __syncthreads();
        part[t] += add;
        __syncthreads();
    }
    int run = part[t] - s;   // exclusive prefix
    for (int i = 0; i < 49; i++) {
        int idx = base + i;
        if (idx < NN) {
            g_rowptr[idx] = run;
            run += g_cnt[idx];
        }
    }
    if (t == 1023) g_rowptr[NN] = EE;
}

// atomic-free fill: slot = rowptr[dst] + eoff[e]
__global__ void __launch_bounds__(256) fill_kernel(const int* __restrict__ edge)
{
    int i = blockIdx.x * 256 + threadIdx.x;
    if (i >= EE / 4) return;
    int4 s4 = __ldg(reinterpret_cast<const int4*>(edge) + i);
    int4 d4 = __ldg(reinterpret_cast<const int4*>(edge + EE) + i);
    int4 o4 = *reinterpret_cast<const int4*>(g_eoff + 4 * i);
    g_esrc[__ldg(g_rowptr + d4.x) + o4.x] = s4.x;
    g_esrc[__ldg(g_rowptr + d4.y) + o4.y] = s4.y;
    g_esrc[__ldg(g_rowptr + d4.z) + o4.z] = s4.z;
    g_esrc[__ldg(g_rowptr + d4.w) + o4.w] = s4.w;
}

// ---------------- gather aggregation + bf16 split (warp per node) -----------
__global__ void __launch_bounds__(256) gather_kernel()
{
    int node = blockIdx.x * 8 + (threadIdx.x >> 5);
    int lane = threadIdx.x & 31;
    int start = __ldg(g_rowptr + node);
    int end   = __ldg(g_rowptr + node + 1);
    float4 a = make_float4(0.f, 0.f, 0.f, 0.f);
    int i = start;
    for (; i + 3 < end; i += 4) {
        int s0 = __ldg(g_esrc + i);
        int s1 = __ldg(g_esrc + i + 1);
        int s2 = __ldg(g_esrc + i + 2);
        int s3 = __ldg(g_esrc + i + 3);
        float4 v0 = ld4(g_x + (long long)s0 * DD + lane * 4);
        float4 v1 = ld4(g_x + (long long)s1 * DD + lane * 4);
        float4 v2 = ld4(g_x + (long long)s2 * DD + lane * 4);
        float4 v3 = ld4(g_x + (long long)s3 * DD + lane * 4);
        a.x += v0.x + v1.x + v2.x + v3.x;
        a.y += v0.y + v1.y + v2.y + v3.y;
        a.z += v0.z + v1.z + v2.z + v3.z;
        a.w += v0.w + v1.w + v2.w + v3.w;
    }
    for (; i < end; i++) {
        int s0 = __ldg(g_esrc + i);
        float4 v0 = ld4(g_x + (long long)s0 * DD + lane * 4);
        a.x += v0.x; a.y += v0.y; a.z += v0.z; a.w += v0.w;
    }
    u32 h0, l0, h1, l1;
    split2(a.x, a.y, h0, l0);
    split2(a.z, a.w, h1, l1);
    long long base = (long long)node * DD + lane * 4;
    *reinterpret_cast<uint2*>(g_ah + base) = make_uint2(h0, h1);
    *reinterpret_cast<uint2*>(g_al + base) = make_uint2(l0, l1);
}

// ---------------- weight split + transpose (runs once per launch) ------------
__global__ void __launch_bounds__(256) split_w_kernel(
    const float* __restrict__ Wl, const float* __restrict__ Wr)
{
    int idx = blockIdx.x * 256 + threadIdx.x;       // 3*128*128 = 49152
    if (idx >= 3 * DD * DD) return;
    int l = idx / (DD * DD);
    int k = (idx / DD) % DD;
    int n = idx % DD;
    int dst = l * DD * DD + n * DD + k;             // transposed [l][n][k]
    float wl = Wl[idx];
    __nv_bfloat16 h = __float2bfloat16(wl);
    g_Wlh[dst] = h;
    g_Wll[dst] = __float2bfloat16(wl - __bfloat162float(h));
    float wr = Wr[idx];
    __nv_bfloat16 h2 = __float2bfloat16(wr);
    g_Wrh[dst] = h2;
    g_Wrl[dst] = __float2bfloat16(wr - __bfloat162float(h2));
}

// ---------------- zero padding rows of buffers (once per launch) -------------
__global__ void __launch_bounds__(256) pad_zero_kernel()
{
    int i = blockIdx.x * 256 + threadIdx.x;         // (NP-NN)*128 = 38912
    if (i >= (NP - NN) * DD) return;
    long long off = (long long)NN * DD + i;
    g_x[off] = 0.f;
    __nv_bfloat16 z = __float2bfloat16(0.f);
    g_xh[off] = z;
    g_xl[off] = z;
    g_ah[off] = z;
    g_al[off] = z;
}

// ---------------- embedding + LayerNorm (writes fp32 + bf16 hi/lo) ----------
__global__ void __launch_bounds__(256) embed_ln_kernel(
    const float* __restrict__ node_emb, const int* __restrict__ pos,
    const float* __restrict__ pos_table, const float* __restrict__ gamma,
    const float* __restrict__ beta)
{
    int row  = blockIdx.x * 8 + (threadIdx.x >> 5);
    int lane = threadIdx.x & 31;
    int p = __ldg(pos + row);
    float4 a  = ld4(node_emb + (long long)row * DD + lane * 4);
    float4 pe = ld4(pos_table + (long long)p * DD + lane * 4);
    float v0 = a.x * SQRTD + pe.x;
    float v1 = a.y * SQRTD + pe.y;
    float v2 = a.z * SQRTD + pe.z;
    float v3 = a.w * SQRTD + pe.w;
    float s  = v0 + v1 + v2 + v3;
    float sq = v0*v0 + v1*v1 + v2*v2 + v3*v3;
    #pragma unroll
    for (int off = 16; off; off >>= 1) {
        s  += __shfl_xor_sync(0xffffffffu, s,  off);
        sq += __shfl_xor_sync(0xffffffffu, sq, off);
    }
    float mean = s * (1.0f / DD);
    float var  = sq * (1.0f / DD) - mean * mean;
    float rstd = rsqrtf(var + EPS);
    float4 g = ld4(gamma + lane * 4);
    float4 b = ld4(beta  + lane * 4);
    float4 o;
    o.x = (v0 - mean) * rstd * g.x + b.x;
    o.y = (v1 - mean) * rstd * g.y + b.y;
    o.z = (v2 - mean) * rstd * g.z + b.z;
    o.w = (v3 - mean) * rstd * g.w + b.w;
    long long base = (long long)row * DD + lane * 4;
    *reinterpret_cast<float4*>(g_x + base) = o;
    u32 h0, l0, h1, l1;
    split2(o.x, o.y, h0, l0);
    split2(o.z, o.w, h1, l1);
    *reinterpret_cast<uint2*>(g_xh + base) = make_uint2(h0, h1);
    *reinterpret_cast<uint2*>(g_xl + base) = make_uint2(l0, l1);
}

// ---------------- tensor-core dual GEMM + bias + ReLU + residual + LN --------
// 12 warps, 192-row tile; weights persistent in smem (4 matrices, 68-word
// padded stride, conflict-free B frags). A frags from global, double-buffered.
__global__ void __launch_bounds__(384) sage_mma_kernel(
    const float* __restrict__ bl, const float* __restrict__ gamma,
    const float* __restrict__ beta, int layer, float* __restrict__ out_opt)
{
    extern __shared__ __align__(16) u32 smem[];   // 4 * 8704 words = 136 KB

    int tid  = threadIdx.x;
    int w    = tid >> 5;
    int lane = tid & 31;
    int g    = lane >> 2;        // 0..7
    int c    = lane & 3;         // 0..3
    int row0 = blockIdx.x * 192;
    long long woff = (long long)layer * DD * DD;

    // ---- load 4 weight matrices into smem once ----
    {
        const __nv_bfloat16* wsrc[4] = { g_Wlh + woff, g_Wll + woff,
                                         g_Wrh + woff, g_Wrl + woff };
        #pragma unroll
        for (int m = 0; m < 4; m++) {
            const uint4* s = reinterpret_cast<const uint4*>(wsrc[m]);  // 16/row
            uint4* d = reinterpret_cast<uint4*>(smem) + m * 2176;      // 17/row
            for (int i = tid; i < 2048; i += 384) {
                int n = i >> 4, c4 = i & 15;
                d[n * 17 + c4] = s[i];
            }
        }
    }
    __syncthreads();

    float acc[16][4];
    #pragma unroll
    for (int t = 0; t < 16; t++)
        #pragma unroll
        for (int j = 0; j < 4; j++) acc[t][j] = 0.f;

    int r1 = row0 + w * 16 + g;
    const u32* pah = reinterpret_cast<const u32*>(g_ah) + (long long)r1 * 64;
    const u32* pal = reinterpret_cast<const u32*>(g_al) + (long long)r1 * 64;
    const u32* pxh = reinterpret_cast<const u32*>(g_xh) + (long long)r1 * 64;
    const u32* pxl = reinterpret_cast<const u32*>(g_xl) + (long long)r1 * 64;

    u32 Ah[2][4], Al[2][4], Xh[2][4], Xl[2][4];
    {
        int kw = c;
        Ah[0][0] = pah[kw]; Ah[0][1] = pah[512 + kw]; Ah[0][2] = pah[kw + 4]; Ah[0][3] = pah[512 + kw + 4];
        Al[0][0] = pal[kw]; Al[0][1] = pal[512 + kw]; Al[0][2] = pal[kw + 4]; Al[0][3] = pal[512 + kw + 4];
        Xh[0][0] = pxh[kw]; Xh[0][1] = pxh[512 + kw]; Xh[0][2] = pxh[kw + 4]; Xh[0][3] = pxh[512 + kw + 4];
        Xl[0][0] = pxl[kw]; Xl[0][1] = pxl[512 + kw]; Xl[0][2] = pxl[kw + 4]; Xl[0][3] = pxl[512 + kw + 4];
    }

    #pragma unroll
    for (int ks = 0; ks < 8; ks++) {
        int cur = ks & 1, nxt = cur ^ 1;
        if (ks < 7) {
            int kw = (ks + 1) * 8 + c;
            Ah[nxt][0] = pah[kw]; Ah[nxt][1] = pah[512 + kw]; Ah[nxt][2] = pah[kw + 4]; Ah[nxt][3] = pah[512 + kw + 4];
            Al[nxt][0] = pal[kw]; Al[nxt][1] = pal[512 + kw]; Al[nxt][2] = pal[kw + 4]; Al[nxt][3] = pal[512 + kw + 4];
            Xh[nxt][0] = pxh[kw]; Xh[nxt][1] = pxh[512 + kw]; Xh[nxt][2] = pxh[kw + 4]; Xh[nxt][3] = pxh[512 + kw + 4];
            Xl[nxt][0] = pxl[kw]; Xl[nxt][1] = pxl[512 + kw]; Xl[nxt][2] = pxl[kw + 4]; Xl[nxt][3] = pxl[512 + kw + 4];
        }
        int kwb = ks * 8 + c;
        #pragma unroll
        for (int t = 0; t < 16; t++) {
            int b0 = (t * 8 + g) * 68 + kwb;
            u32 wlh[2] = { smem[b0],         smem[b0 + 4] };
            u32 wll[2] = { smem[8704 + b0],  smem[8704 + b0 + 4] };
            u32 wrh[2] = { smem[17408 + b0], smem[17408 + b0 + 4] };
            u32 wrl[2] = { smem[26112 + b0], smem[26112 + b0 + 4] };
            mma16816(acc[t], Ah[cur], wlh);
            mma16816(acc[t], Al[cur], wlh);
            mma16816(acc[t], Ah[cur], wll);
            mma16816(acc[t], Xh[cur], wrh);
            mma16816(acc[t], Xl[cur], wrh);
            mma16816(acc[t], Xh[cur], wrl);
        }
    }

    // ---- epilogue: bias + relu + residual + LayerNorm ----
    int r2 = r1 + 8;
    float v[16][4];
    #pragma unroll
    for (int t = 0; t < 16; t++) {
        int col = t * 8 + c * 2;
        float2 bb = *reinterpret_cast<const float2*>(bl + col);
        float2 xa = *reinterpret_cast<const float2*>(g_x + (long long)r1 * DD + col);
        float2 xb = *reinterpret_cast<const float2*>(g_x + (long long)r2 * DD + col);
        v[t][0] = fmaxf(acc[t][0] + bb.x, 0.f) + xa.x;
        v[t][1] = fmaxf(acc[t][1] + bb.y, 0.f) + xa.y;
        v[t][2] = fmaxf(acc[t][2] + bb.x, 0.f) + xb.x;
        v[t][3] = fmaxf(acc[t][3] + bb.y, 0.f) + xb.y;
    }
    float s1 = 0.f, q1 = 0.f, s2 = 0.f, q2 = 0.f;
    #pragma unroll
    for (int t = 0; t < 16; t++) {
        s1 += v[t][0] + v[t][1];
        q1 += v[t][0] * v[t][0] + v[t][1] * v[t][1];
        s2 += v[t][2] + v[t][3];
        q2 += v[t][2] * v[t][2] + v[t][3] * v[t][3];
    }
    #pragma unroll
    for (int m = 1; m <= 2; m <<= 1) {
        s1 += __shfl_xor_sync(0xffffffffu, s1, m);
        q1 += __shfl_xor_sync(0xffffffffu, q1, m);
        s2 += __shfl_xor_sync(0xffffffffu, s2, m);
        q2 += __shfl_xor_sync(0xffffffffu, q2, m);
    }
    float mean1 = s1 * (1.0f / DD);
    float var1  = q1 * (1.0f / DD) - mean1 * mean1;
    float rs1   = rsqrtf(var1 + EPS);
    float mean2 = s2 * (1.0f / DD);
    float var2  = q2 * (1.0f / DD) - mean2 * mean2;
    float rs2   = rsqrtf(var2 + EPS);

    bool final = (out_opt != nullptr);
    #pragma unroll
    for (int t = 0; t < 16; t++) {
        int col = t * 8 + c * 2;
        float2 gg = *reinterpret_cast<const float2*>(gamma + col);
        float2 be = *reinterpret_cast<const float2*>(beta + col);
        float2 o1, o2;
        o1.x = (v[t][0] - mean1) * rs1 * gg.x + be.x;
        o1.y = (v[t][1] - mean1) * rs1 * gg.y + be.y;
        o2.x = (v[t][2] - mean2) * rs2 * gg.x + be.x;
        o2.y = (v[t][3] - mean2) * rs2 * gg.y + be.y;
        if (final) {
            if (r1 < NN)
                *reinterpret_cast<float2*>(out_opt + (long long)r1 * DD + col) = o1;
            if (r2 < NN)
                *reinterpret_cast<float2*>(out_opt + (long long)r2 * DD + col) = o2;
        } else {
            *reinterpret_cast<float2*>(g_x + (long long)r1 * DD + col) = o1;
            *reinterpret_cast<float2*>(g_x + (long long)r2 * DD + col) = o2;
            u32 h, l;
            split2(o1.x, o1.y, h, l);
            *reinterpret_cast<u32*>(g_xh + (long long)r1 * DD + col) = h;
            *reinterpret_cast<u32*>(g_xl + (long long)r1 * DD + col) = l;
            split2(o2.x, o2.y, h, l);
            *reinterpret_cast<u32*>(g_xh + (long long)r2 * DD + col) = h;
            *reinterpret_cast<u32*>(g_xl + (long long)r2 * DD + col) = l;
        }
    }
}

extern "C" void kernel_launch(void* const* d_in, const int* in_sizes, int n_in,
                              void* d_out, int out_size)
{
    const float* node_emb  = (const float*)d_in[0];
    const int*   pos       = (const int*)  d_in[1];
    const int*   edge      = (const int*)  d_in[2];
    const float* pos_table = (const float*)d_in[3];
    const float* Wl        = (const float*)d_in[4];
    const float* bl        = (const float*)d_in[5];
    const float* Wr        = (const float*)d_in[6];
    const float* emb_g     = (const float*)d_in[7];
    const float* emb_b     = (const float*)d_in[8];
    const float* hid_g     = (const float*)d_in[9];
    const float* hid_b     = (const float*)d_in[10];
    float* out = (float*)d_out;

    const int SMEM = 4 * 8704 * 4;  // 139264 bytes
    cudaFuncSetAttribute(sage_mma_kernel,
                         cudaFuncAttributeMaxDynamicSharedMemorySize, SMEM);

    // CSR build (once per launch)
    zero_cnt_kernel<<<196, 256>>>();
    hist_off_kernel<<<(EE / 4 + 255) / 256, 256>>>(edge);
    scan_kernel<<<1, 1024>>>();
    fill_kernel<<<(EE / 4 + 255) / 256, 256>>>(edge);

    pad_zero_kernel<<<152, 256>>>();
    split_w_kernel<<<192, 256>>>(Wl, Wr);
    embed_ln_kernel<<<NN / 8, 256>>>(node_emb, pos, pos_table, emb_g, emb_b);

    const int gath_grid = NN / 8;             // 6250
    const int gemm_grid = NP / 192;           // 262

    for (int l = 0; l < 3; l++) {
        gather_kernel<<<gath_grid, 256>>>();
        float* outp = (l == 2) ? out : nullptr;
        sage_mma_kernel<<<gemm_grid, 384, SMEM>>>(
            bl + l * DD, hid_g + l * DD, hid_b + l * DD, l, outp);
    }
}